// round 4
// baseline (speedup 1.0000x reference)
#include <cuda_runtime.h>
#include <cuda_bf16.h>
#include <math.h>

#define B4      4
#define C256    256
#define HW      64
#define NPIX    (HW*HW)          // 4096
#define IMG     (C256*NPIX)      // per-batch fp32 elements
#define COUT_CO 216
#define DCN_K   2304             // 256*9

typedef unsigned long long u64t;

// f32x2 helpers (Blackwell packed fp32: 2 FMAs per issue slot, sm_100+ / PTX 8.6)
__device__ __forceinline__ u64t dup2(float v) {
    u64t r; asm("mov.b64 %0,{%1,%1};" : "=l"(r) : "f"(v)); return r;
}
__device__ __forceinline__ void ffma2(u64t& d, u64t a, u64t b) {
    asm("fma.rn.f32x2 %0,%1,%2,%0;" : "+l"(d) : "l"(a), "l"(b));
}
__device__ __forceinline__ float2 unpk2(u64t v) {
    float2 r; asm("mov.b64 {%0,%1},%2;" : "=f"(r.x), "=f"(r.y) : "l"(v)); return r;
}

// Scratch (no allocation allowed -> __device__ globals)
__device__ float g_bufA[B4*IMG];
__device__ float g_bufB[B4*IMG];
__device__ float g_co  [B4*COUT_CO*NPIX];
__device__ float g_col [DCN_K*NPIX];      // single-batch im2col (37.7MB, L2-resident)
__device__ float g_stats[B4*32*2];

// ---------------------------------------------------------------------------
// 1) bilinear half-downsample = 2x2 average at these shapes (float2 loads)
// ---------------------------------------------------------------------------
__global__ void resize_half_kernel(const float* __restrict__ in, float* __restrict__ out) {
    int idx = blockIdx.x * 256 + threadIdx.x;
    int x = idx & 63, y = (idx >> 6) & 63, cg = idx >> 12;
    const float2* p = (const float2*)(in + (size_t)cg * (128 * 128));
    int yy = 2 * y;
    float2 a = p[yy * 64 + x];
    float2 b = p[(yy + 1) * 64 + x];
    out[idx] = 0.25f * (a.x + a.y + b.x + b.y);
}

// ---------------------------------------------------------------------------
// 2) 3x3 conv, pad 1, FFMA2 over oc-pairs.
//    grid: (16 tiles, ceil(Cout/32), B); 256 thr; thread = 2 oc-pairs x 8 px
//    Weights in smem pre-interleaved as (oc_even, oc_odd) u64 pairs
//    -> LDS.64 broadcast, no pack instructions for weights.
// ---------------------------------------------------------------------------
__global__ __launch_bounds__(256, 2)
void conv3x3_kernel(const float* __restrict__ in, const float* __restrict__ w,
                    const float* __restrict__ bias, float* __restrict__ out,
                    int Cin, int Cout) {
    const int b    = blockIdx.z;
    const int ocb  = blockIdx.y;
    const int tile = blockIdx.x;
    const int ty0  = (tile >> 2) * 16, tx0 = (tile & 3) * 16;
    const int tid  = threadIdx.x;
    const int ocg  = tid >> 5;                   // warp id: 2 oc-pairs (4 oc)
    const int pg   = tid & 31;
    const int px0  = (pg & 7) * 2, py0 = (pg >> 3) * 4;

    __shared__ float s_in[4 * 324];              // 4 ch x 18x18
    __shared__ float s_w[32 * 36];               // pair-interleaved: ((pair*36+r)*2+half)

    u64t acc[16];                                // [pair(2)][j(4)][i(2)]
#pragma unroll
    for (int i = 0; i < 16; i++) acc[i] = 0ull;

    const float* inb = in + (size_t)b * Cin * NPIX;
    const size_t wstride = (size_t)Cin * 9;

    for (int c0 = 0; c0 < Cin; c0 += 4) {
        __syncthreads();
        for (int t = tid; t < 4 * 324; t += 256) {
            int cl = t / 324, r = t - cl * 324;
            int yy = r / 18 - 1 + ty0;
            int xx = r % 18 - 1 + tx0;
            float v = 0.f;
            if (yy >= 0 && yy < HW && xx >= 0 && xx < HW)
                v = inb[(size_t)(c0 + cl) * NPIX + yy * HW + xx];
            s_in[t] = v;
        }
        for (int t = tid; t < 32 * 36; t += 256) {
            int ol = t / 36, r = t - ol * 36;
            int oc = ocb * 32 + ol;
            float v = (oc < Cout) ? w[(size_t)oc * wstride + (size_t)c0 * 9 + r] : 0.f;
            s_w[((ol >> 1) * 36 + r) * 2 + (ol & 1)] = v;
        }
        __syncthreads();

#pragma unroll
        for (int cl = 0; cl < 4; cl++) {
            u64t wv[24];                         // duplicated input window 6x4
#pragma unroll
            for (int r = 0; r < 6; r++)
#pragma unroll
                for (int cc = 0; cc < 4; cc++)
                    wv[r * 4 + cc] = dup2(s_in[cl * 324 + (py0 + r) * 18 + px0 + cc]);
#pragma unroll
            for (int p = 0; p < 2; p++) {
                int pairIdx = ocg * 2 + p;
                const u64t* wp = (const u64t*)&s_w[(pairIdx * 36 + cl * 9) * 2];
                u64t wk[9];
#pragma unroll
                for (int k = 0; k < 9; k++) wk[k] = wp[k];
#pragma unroll
                for (int ki = 0; ki < 3; ki++)
#pragma unroll
                    for (int kj = 0; kj < 3; kj++)
#pragma unroll
                        for (int j = 0; j < 4; j++)
#pragma unroll
                            for (int i = 0; i < 2; i++)
                                ffma2(acc[p * 8 + j * 2 + i],
                                      wv[(j + ki) * 4 + (i + kj)], wk[ki * 3 + kj]);
            }
        }
    }

#pragma unroll
    for (int p = 0; p < 2; p++) {
        int oc0 = ocb * 32 + ocg * 4 + p * 2;    // even oc of this pair
#pragma unroll
        for (int j = 0; j < 4; j++)
#pragma unroll
            for (int i = 0; i < 2; i++) {
                float2 v = unpk2(acc[p * 8 + j * 2 + i]);
                int oy = ty0 + py0 + j, ox = tx0 + px0 + i;
                if (oc0 < Cout)
                    out[((size_t)b * Cout + oc0) * NPIX + oy * HW + ox] = v.x + bias[oc0];
                if (oc0 + 1 < Cout)
                    out[((size_t)b * Cout + oc0 + 1) * NPIX + oy * HW + ox] = v.y + bias[oc0 + 1];
            }
    }
}

// ---------------------------------------------------------------------------
// 3) 1x1 conv / GEMM with FFMA2 over pixel-pairs.
//    grid: (8 px-tiles of 512, Cout/32, B or 1); thread = 8 oc x 4 px-pairs
// ---------------------------------------------------------------------------
__global__ __launch_bounds__(256, 2)
void gemm_conv_kernel(const float* __restrict__ inA, const float* __restrict__ inB,
                      int splitK, int K,
                      const float* __restrict__ w, const float* __restrict__ bias,
                      float* __restrict__ out, int Cout) {
    const int b   = blockIdx.z;
    const int ocb = blockIdx.y;
    const int px_base = blockIdx.x * 512;
    const int tid  = threadIdx.x;
    const int oc_g = tid >> 6;                   // 0..3 (8 oc each)
    const int pxg  = tid & 63;                   // 8 px each

    __shared__ float s_in[8 * 512];
    __shared__ float s_w[8 * 32];

    u64t acc[32];                                // [o(8)][pp(4)]
#pragma unroll
    for (int o = 0; o < 8; o++) {
        int oc = ocb * 32 + oc_g * 8 + o;
        u64t binit = (oc < Cout) ? dup2(bias[oc]) : 0ull;
#pragma unroll
        for (int pp = 0; pp < 4; pp++) acc[o * 4 + pp] = binit;
    }

    for (int k0 = 0; k0 < K; k0 += 8) {
        __syncthreads();
        for (int t = tid; t < 8 * 128; t += 256) {
            int row = t >> 7, c4 = t & 127;
            int k = k0 + row;
            const float* src;
            if (k < splitK) src = inA + ((size_t)b * splitK + k) * NPIX;
            else            src = inB + ((size_t)b * (K - splitK) + (k - splitK)) * NPIX;
            float4 v = *(const float4*)(src + px_base + c4 * 4);
            *(float4*)&s_in[row * 512 + c4 * 4] = v;
        }
        {
            int kk = tid >> 5, ol = tid & 31;
            int oc = ocb * 32 + ol;
            s_w[kk * 32 + ol] = (oc < Cout) ? w[(size_t)oc * K + k0 + kk] : 0.f;
        }
        __syncthreads();

#pragma unroll
        for (int kk = 0; kk < 8; kk++) {
            u64t iv[4];
#pragma unroll
            for (int pp = 0; pp < 4; pp++)
                iv[pp] = *(const u64t*)&s_in[kk * 512 + pxg * 8 + pp * 2];
            u64t wv[8];
#pragma unroll
            for (int o = 0; o < 8; o++) wv[o] = dup2(s_w[kk * 32 + oc_g * 8 + o]);
#pragma unroll
            for (int o = 0; o < 8; o++)
#pragma unroll
                for (int pp = 0; pp < 4; pp++)
                    ffma2(acc[o * 4 + pp], iv[pp], wv[o]);
        }
    }

#pragma unroll
    for (int o = 0; o < 8; o++) {
        int oc = ocb * 32 + oc_g * 8 + o;
        if (oc >= Cout) continue;
        float* op = out + ((size_t)b * Cout + oc) * NPIX + px_base + pxg * 8;
#pragma unroll
        for (int pp = 0; pp < 4; pp++) {
            float2 v = unpk2(acc[o * 4 + pp]);
            *(float2*)(op + pp * 2) = v;
        }
    }
}

// ---------------------------------------------------------------------------
// 4) GroupNorm stats: one block (512 thr) per (b,g), float4 loads
// ---------------------------------------------------------------------------
__global__ __launch_bounds__(512)
void gn_stats_kernel(const float* __restrict__ x, float* __restrict__ stats) {
    int bg = blockIdx.x;
    const float4* p = (const float4*)(x + (size_t)bg * 32768);
    float s = 0.f, ss = 0.f;
    for (int i = threadIdx.x; i < 8192; i += 512) {
        float4 v = p[i];
        s += v.x + v.y + v.z + v.w;
        ss = fmaf(v.x, v.x, fmaf(v.y, v.y, fmaf(v.z, v.z, fmaf(v.w, v.w, ss))));
    }
#pragma unroll
    for (int o = 16; o > 0; o >>= 1) {
        s  += __shfl_down_sync(0xffffffffu, s, o);
        ss += __shfl_down_sync(0xffffffffu, ss, o);
    }
    __shared__ float sh[32];
    int wrp = threadIdx.x >> 5, lane = threadIdx.x & 31;
    if (lane == 0) { sh[wrp] = s; sh[wrp + 16] = ss; }
    __syncthreads();
    if (threadIdx.x == 0) {
        float S = 0.f, SS = 0.f;
#pragma unroll
        for (int i = 0; i < 16; i++) { S += sh[i]; SS += sh[i + 16]; }
        float mu  = S * (1.f / 32768.f);
        float var = SS * (1.f / 32768.f) - mu * mu;
        stats[bg * 2]     = mu;
        stats[bg * 2 + 1] = rsqrtf(var + 1e-6f);
    }
}

// ---------------------------------------------------------------------------
// 5) GN apply + SiLU, float4
// ---------------------------------------------------------------------------
__global__ void gn_apply_silu_kernel(const float* __restrict__ x, const float* __restrict__ stats,
                                     const float* __restrict__ gamma, const float* __restrict__ beta,
                                     float* __restrict__ out) {
    int idx = blockIdx.x * 256 + threadIdx.x;     // over 4*IMG/4
    int cg = idx >> 10;                           // 1024 float4 per channel-img
    int c = cg & 255;
    int bg = (cg >> 8) * 32 + (c >> 3);
    float mu = stats[bg * 2], rs = stats[bg * 2 + 1];
    float ga = gamma[c], be = beta[c];
    float4 v = ((const float4*)x)[idx];
    float4 r;
    float t;
    t = fmaf((v.x - mu) * rs, ga, be); r.x = t * (1.f / (1.f + __expf(-t)));
    t = fmaf((v.y - mu) * rs, ga, be); r.y = t * (1.f / (1.f + __expf(-t)));
    t = fmaf((v.z - mu) * rs, ga, be); r.z = t * (1.f / (1.f + __expf(-t)));
    t = fmaf((v.w - mu) * rs, ga, be); r.w = t * (1.f / (1.f + __expf(-t)));
    ((float4*)out)[idx] = r;
}

// ---------------------------------------------------------------------------
// 6) 7x7 depthwise conv, pad 3
// ---------------------------------------------------------------------------
__global__ __launch_bounds__(256)
void dwconv7x7_kernel(const float* __restrict__ x, const float* __restrict__ w,
                      const float* __restrict__ bias, float* __restrict__ out) {
    int bc = blockIdx.x;
    int c = bc & 255;
    const float* p = x + (size_t)bc * NPIX;
    __shared__ float s[70 * 70];
    __shared__ float sw[49];
    for (int t = threadIdx.x; t < 70 * 70; t += 256) {
        int yy = t / 70 - 3, xx = t % 70 - 3;
        s[t] = (yy >= 0 && yy < HW && xx >= 0 && xx < HW) ? p[yy * HW + xx] : 0.f;
    }
    if (threadIdx.x < 49) sw[threadIdx.x] = w[c * 49 + threadIdx.x];
    float bb = bias[c];
    __syncthreads();
    for (int t = threadIdx.x; t < NPIX; t += 256) {
        int y = t >> 6, xq = t & 63;
        float a = bb;
#pragma unroll
        for (int i = 0; i < 7; i++)
#pragma unroll
            for (int j = 0; j < 7; j++)
                a = fmaf(sw[i * 7 + j], s[(y + i) * 70 + xq + j], a);
        out[(size_t)bc * NPIX + t] = a;
    }
}

// ---------------------------------------------------------------------------
// 7) DCN im2col, single batch (pointers pre-offset by caller)
// ---------------------------------------------------------------------------
__global__ __launch_bounds__(256)
void dcn_im2col_kernel(const float* __restrict__ x, const float* __restrict__ co,
                       float* __restrict__ col) {
    const int gk = blockIdx.y;
    const int g  = gk / 9, k = gk - g * 9;
    const int px = blockIdx.x * 256 + threadIdx.x;
    const int y  = px >> 6, xp = px & 63;

    float dy = co[(size_t)(g * 18 + 2 * k)     * NPIX + px];
    float dx = co[(size_t)(g * 18 + 2 * k + 1) * NPIX + px];
    float mv = co[(size_t)(144 + g * 9 + k)    * NPIX + px];
    float m  = 1.f / (1.f + __expf(-mv));

    float py  = (float)(y  - 1 + k / 3) + dy;
    float pxf = (float)(xp - 1 + k % 3) + dx;
    float y0f = floorf(py), x0f = floorf(pxf);
    float wy = py - y0f, wx = pxf - x0f;
    int y0 = (int)y0f, x0 = (int)x0f;

    bool vy0 = (y0 >= 0)     && (y0 < HW);
    bool vy1 = (y0 + 1 >= 0) && (y0 + 1 < HW);
    bool vx0 = (x0 >= 0)     && (x0 < HW);
    bool vx1 = (x0 + 1 >= 0) && (x0 + 1 < HW);

    float m00 = (vy0 && vx0) ? m * (1.f - wy) * (1.f - wx) : 0.f;
    float m01 = (vy0 && vx1) ? m * (1.f - wy) * wx         : 0.f;
    float m10 = (vy1 && vx0) ? m * wy * (1.f - wx)         : 0.f;
    float m11 = (vy1 && vx1) ? m * wy * wx                 : 0.f;

    int iy0 = min(max(y0, 0), HW - 1), iy1 = min(max(y0 + 1, 0), HW - 1);
    int ix0 = min(max(x0, 0), HW - 1), ix1 = min(max(x0 + 1, 0), HW - 1);
    int i00 = iy0 * HW + ix0, i01 = iy0 * HW + ix1;
    int i10 = iy1 * HW + ix0, i11 = iy1 * HW + ix1;

    const float* xb = x + (size_t)(g * 32) * NPIX;
    float* colb = col + ((size_t)(g * 32) * 9 + k) * NPIX + px;

#pragma unroll 4
    for (int c = 0; c < 32; c++) {
        const float* xc = xb + (size_t)c * NPIX;
        float v = m00 * xc[i00] + m01 * xc[i01] + m10 * xc[i10] + m11 * xc[i11];
        colb[(size_t)c * 9 * NPIX] = v;
    }
}

// ---------------------------------------------------------------------------
// Launch
// ---------------------------------------------------------------------------
extern "C" void kernel_launch(void* const* d_in, const int* in_sizes, int n_in,
                              void* d_out, int out_size) {
    const float* x_main = (const float*)d_in[0];
    const float* prior  = (const float*)d_in[1];
    const float* ds_w = (const float*)d_in[2];  const float* ds_b = (const float*)d_in[3];
    const float* w1a  = (const float*)d_in[4];  const float* b1a  = (const float*)d_in[5];
    const float* g1a  = (const float*)d_in[6];  const float* be1a = (const float*)d_in[7];
    const float* w1b  = (const float*)d_in[8];  const float* b1b  = (const float*)d_in[9];
    const float* g1b  = (const float*)d_in[10]; const float* be1b = (const float*)d_in[11];
    const float* w1c  = (const float*)d_in[12]; const float* b1c  = (const float*)d_in[13];
    const float* w2   = (const float*)d_in[14]; const float* b2   = (const float*)d_in[15];
    const float* g2   = (const float*)d_in[16]; const float* be2  = (const float*)d_in[17];
    const float* co_w = (const float*)d_in[18]; const float* co_b = (const float*)d_in[19];
    const float* dcn_w= (const float*)d_in[20]; const float* dcn_b= (const float*)d_in[21];

    float *bufA, *bufB, *coBuf, *colBuf, *stats;
    cudaGetSymbolAddress((void**)&bufA,  g_bufA);
    cudaGetSymbolAddress((void**)&bufB,  g_bufB);
    cudaGetSymbolAddress((void**)&coBuf, g_co);
    cudaGetSymbolAddress((void**)&colBuf,g_col);
    cudaGetSymbolAddress((void**)&stats, g_stats);

    float* out_warp = (float*)d_out;
    float* out_feat = out_warp + (size_t)B4 * IMG;

    const int EL_BLOCKS = (B4 * IMG) / 256;
    const int EL4_BLOCKS = (B4 * IMG) / 1024;

    // 1. downsample prior -> bufB
    resize_half_kernel<<<EL_BLOCKS, 256>>>(prior, bufB);
    // 2. ds conv 3x3 -> bufA
    conv3x3_kernel<<<dim3(16, 8, B4), 256>>>(bufB, ds_w, ds_b, bufA, C256, C256);
    // 3. 1x1 conv over concat(pr, x_main) -> bufB
    gemm_conv_kernel<<<dim3(8, 8, B4), 256>>>(bufA, x_main, 256, 512, w1a, b1a, bufB, C256);
    // 4. GN + SiLU (in place)
    gn_stats_kernel<<<B4 * 32, 512>>>(bufB, stats);
    gn_apply_silu_kernel<<<EL4_BLOCKS, 256>>>(bufB, stats, g1a, be1a, bufB);
    // 5. 7x7 depthwise -> bufA
    dwconv7x7_kernel<<<B4 * C256, 256>>>(bufB, w1b, b1b, bufA);
    // 6. GN + SiLU (in place)
    gn_stats_kernel<<<B4 * 32, 512>>>(bufA, stats);
    gn_apply_silu_kernel<<<EL4_BLOCKS, 256>>>(bufA, stats, g1b, be1b, bufA);
    // 7. 1x1 conv -> bufB
    gemm_conv_kernel<<<dim3(8, 8, B4), 256>>>(bufA, nullptr, 256, 256, w1c, b1c, bufB, C256);
    // 8. 3x3 conv (w2) -> bufA
    conv3x3_kernel<<<dim3(16, 8, B4), 256>>>(bufB, w2, b2, bufA, C256, C256);
    // 9. GN + SiLU -> offset_feat
    gn_stats_kernel<<<B4 * 32, 512>>>(bufA, stats);
    gn_apply_silu_kernel<<<EL4_BLOCKS, 256>>>(bufA, stats, g2, be2, out_feat);
    // 10. co conv 3x3 (256 -> 216) -> coBuf
    conv3x3_kernel<<<dim3(16, 7, B4), 256>>>(out_feat, co_w, co_b, coBuf, C256, COUT_CO);
    // 11/12. DCN per batch: im2col(b) then GEMM(b) so col stays in L2
    for (int b = 0; b < B4; b++) {
        dcn_im2col_kernel<<<dim3(16, 72, 1), 256>>>(
            x_main + (size_t)b * IMG,
            coBuf + (size_t)b * COUT_CO * NPIX,
            colBuf);
        gemm_conv_kernel<<<dim3(8, 8, 1), 256>>>(
            colBuf, nullptr, DCN_K, DCN_K, dcn_w, dcn_b,
            out_warp + (size_t)b * IMG, C256);
    }
}

// round 7
// speedup vs baseline: 1.4516x; 1.4516x over previous
#include <cuda_runtime.h>
#include <cuda_bf16.h>
#include <math.h>

#define B4      4
#define C256    256
#define HW      64
#define NPIX    (HW*HW)          // 4096
#define IMG     (C256*NPIX)      // per-batch fp32 elements
#define COUT_CO 216
#define DCN_K   2304             // 256*9

typedef unsigned int u32t;

// ---------------------------------------------------------------------------
// Scratch (no allocation allowed -> __device__ globals)
// ---------------------------------------------------------------------------
__device__ float g_bufA[B4*IMG];
__device__ float g_bufB[B4*IMG];
__device__ float g_co  [B4*COUT_CO*NPIX];
__device__ float g_stats[B4*32*2];
__device__ __nv_bfloat16 g_whi[C256*DCN_K];
__device__ __nv_bfloat16 g_wlo[C256*DCN_K];
__device__ __nv_bfloat16 g_colhi[(size_t)B4*DCN_K*NPIX];
__device__ __nv_bfloat16 g_collo[(size_t)B4*DCN_K*NPIX];

__device__ __forceinline__ u32t smem_u32(const void* p) {
    u32t a;
    asm("{ .reg .u64 t; cvta.to.shared.u64 t, %1; cvt.u32.u64 %0, t; }"
        : "=r"(a) : "l"(p));
    return a;
}

// ---------------------------------------------------------------------------
// 1) bilinear half-downsample = 2x2 average at these shapes
// ---------------------------------------------------------------------------
__global__ void resize_half_kernel(const float* __restrict__ in, float* __restrict__ out) {
    int idx = blockIdx.x * 256 + threadIdx.x;
    int x = idx & 63, y = (idx >> 6) & 63, cg = idx >> 12;
    const float2* p = (const float2*)(in + (size_t)cg * (128 * 128));
    int yy = 2 * y;
    float2 a = p[yy * 64 + x];
    float2 b = p[(yy + 1) * 64 + x];
    out[idx] = 0.25f * (a.x + a.y + b.x + b.y);
}

// ---------------------------------------------------------------------------
// 2) 3x3 conv, pad 1 (Round-1 scalar version, known-good)
// ---------------------------------------------------------------------------
__global__ __launch_bounds__(256)
void conv3x3_kernel(const float* __restrict__ in, const float* __restrict__ w,
                    const float* __restrict__ bias, float* __restrict__ out,
                    int Cin, int Cout) {
    const int b    = blockIdx.z;
    const int ocb  = blockIdx.y;
    const int tile = blockIdx.x;
    const int ty0  = (tile >> 2) * 16, tx0 = (tile & 3) * 16;
    const int tid  = threadIdx.x;
    const int oc_g = tid >> 5;
    const int pg   = tid & 31;
    const int px0  = (pg & 7) * 2, py0 = (pg >> 3) * 4;

    __shared__ float s_in[4 * 324];
    __shared__ float s_w[32 * 36];

    float acc[32];
#pragma unroll
    for (int i = 0; i < 32; i++) acc[i] = 0.f;

    const float* inb = in + (size_t)b * Cin * NPIX;
    const size_t wstride = (size_t)Cin * 9;

    for (int c0 = 0; c0 < Cin; c0 += 4) {
        __syncthreads();
        for (int t = tid; t < 4 * 324; t += 256) {
            int cl = t / 324, r = t - cl * 324;
            int yy = r / 18 - 1 + ty0;
            int xx = r % 18 - 1 + tx0;
            float v = 0.f;
            if (yy >= 0 && yy < HW && xx >= 0 && xx < HW)
                v = inb[(size_t)(c0 + cl) * NPIX + yy * HW + xx];
            s_in[t] = v;
        }
        for (int t = tid; t < 32 * 36; t += 256) {
            int ol = t / 36, r = t - ol * 36;
            int oc = ocb * 32 + ol;
            s_w[t] = (oc < Cout) ? w[(size_t)oc * wstride + (size_t)c0 * 9 + r] : 0.f;
        }
        __syncthreads();

#pragma unroll
        for (int cl = 0; cl < 4; cl++) {
            float win[24];
#pragma unroll
            for (int r = 0; r < 6; r++)
#pragma unroll
                for (int cc = 0; cc < 4; cc++)
                    win[r * 4 + cc] = s_in[cl * 324 + (py0 + r) * 18 + px0 + cc];
#pragma unroll
            for (int o = 0; o < 4; o++) {
                const float* wp = &s_w[(oc_g * 4 + o) * 36 + cl * 9];
                float w0 = wp[0], w1 = wp[1], w2 = wp[2];
                float w3 = wp[3], w4 = wp[4], w5 = wp[5];
                float w6 = wp[6], w7 = wp[7], w8 = wp[8];
#pragma unroll
                for (int j = 0; j < 4; j++)
#pragma unroll
                    for (int i = 0; i < 2; i++) {
                        float s = acc[o * 8 + j * 2 + i];
                        s = fmaf(w0, win[j*4 + i    ], s);
                        s = fmaf(w1, win[j*4 + i + 1], s);
                        s = fmaf(w2, win[j*4 + i + 2], s);
                        s = fmaf(w3, win[(j+1)*4 + i    ], s);
                        s = fmaf(w4, win[(j+1)*4 + i + 1], s);
                        s = fmaf(w5, win[(j+1)*4 + i + 2], s);
                        s = fmaf(w6, win[(j+2)*4 + i    ], s);
                        s = fmaf(w7, win[(j+2)*4 + i + 1], s);
                        s = fmaf(w8, win[(j+2)*4 + i + 2], s);
                        acc[o * 8 + j * 2 + i] = s;
                    }
            }
        }
    }

#pragma unroll
    for (int o = 0; o < 4; o++) {
        int oc = ocb * 32 + oc_g * 4 + o;
        if (oc >= Cout) continue;
        float bb = bias[oc];
        float* op = out + ((size_t)b * Cout + oc) * NPIX;
#pragma unroll
        for (int j = 0; j < 4; j++)
#pragma unroll
            for (int i = 0; i < 2; i++) {
                int oy = ty0 + py0 + j, ox = tx0 + px0 + i;
                op[oy * HW + ox] = acc[o * 8 + j * 2 + i] + bb;
            }
    }
}

// ---------------------------------------------------------------------------
// 3) 1x1 conv / GEMM (Round-1 scalar version, known-good)
// ---------------------------------------------------------------------------
__global__ __launch_bounds__(256)
void gemm_conv_kernel(const float* __restrict__ inA, const float* __restrict__ inB,
                      int splitK, int K,
                      const float* __restrict__ w, const float* __restrict__ bias,
                      float* __restrict__ out, int Cout) {
    const int b   = blockIdx.z;
    const int ocb = blockIdx.y;
    const int px_base = blockIdx.x * 512;
    const int tid  = threadIdx.x;
    const int oc_g = tid >> 6;
    const int pxg  = tid & 63;

    __shared__ float s_in[8 * 512];
    __shared__ float s_w[8 * 32];

    float acc[64];
#pragma unroll
    for (int i = 0; i < 64; i++) acc[i] = 0.f;

    for (int k0 = 0; k0 < K; k0 += 8) {
        __syncthreads();
        for (int t = tid; t < 8 * 128; t += 256) {
            int row = t >> 7, c4 = t & 127;
            int k = k0 + row;
            const float* src;
            if (k < splitK) src = inA + ((size_t)b * splitK + k) * NPIX;
            else            src = inB + ((size_t)b * (K - splitK) + (k - splitK)) * NPIX;
            float4 v = *(const float4*)(src + px_base + c4 * 4);
            *(float4*)&s_in[row * 512 + c4 * 4] = v;
        }
        {
            int kk = tid >> 5, ol = tid & 31;
            int oc = ocb * 32 + ol;
            s_w[kk * 32 + ol] = (oc < Cout) ? w[(size_t)oc * K + k0 + kk] : 0.f;
        }
        __syncthreads();

#pragma unroll
        for (int kk = 0; kk < 8; kk++) {
            float wv[8], iv[8];
#pragma unroll
            for (int o = 0; o < 8; o++) wv[o] = s_w[kk * 32 + oc_g * 8 + o];
#pragma unroll
            for (int p = 0; p < 8; p++) iv[p] = s_in[kk * 512 + pxg * 8 + p];
#pragma unroll
            for (int o = 0; o < 8; o++)
#pragma unroll
                for (int p = 0; p < 8; p++)
                    acc[o * 8 + p] = fmaf(wv[o], iv[p], acc[o * 8 + p]);
        }
    }

#pragma unroll
    for (int o = 0; o < 8; o++) {
        int oc = ocb * 32 + oc_g * 8 + o;
        if (oc >= Cout) continue;
        float bb = bias[oc];
        float* op = out + ((size_t)b * Cout + oc) * NPIX + px_base + pxg * 8;
#pragma unroll
        for (int p = 0; p < 8; p++) op[p] = acc[o * 8 + p] + bb;
    }
}

// ---------------------------------------------------------------------------
// 4) GroupNorm stats
// ---------------------------------------------------------------------------
__global__ __launch_bounds__(512)
void gn_stats_kernel(const float* __restrict__ x, float* __restrict__ stats) {
    int bg = blockIdx.x;
    const float4* p = (const float4*)(x + (size_t)bg * 32768);
    float s = 0.f, ss = 0.f;
    for (int i = threadIdx.x; i < 8192; i += 512) {
        float4 v = p[i];
        s += v.x + v.y + v.z + v.w;
        ss = fmaf(v.x, v.x, fmaf(v.y, v.y, fmaf(v.z, v.z, fmaf(v.w, v.w, ss))));
    }
#pragma unroll
    for (int o = 16; o > 0; o >>= 1) {
        s  += __shfl_down_sync(0xffffffffu, s, o);
        ss += __shfl_down_sync(0xffffffffu, ss, o);
    }
    __shared__ float sh[32];
    int wrp = threadIdx.x >> 5, lane = threadIdx.x & 31;
    if (lane == 0) { sh[wrp] = s; sh[wrp + 16] = ss; }
    __syncthreads();
    if (threadIdx.x == 0) {
        float S = 0.f, SS = 0.f;
#pragma unroll
        for (int i = 0; i < 16; i++) { S += sh[i]; SS += sh[i + 16]; }
        float mu  = S * (1.f / 32768.f);
        float var = SS * (1.f / 32768.f) - mu * mu;
        stats[bg * 2]     = mu;
        stats[bg * 2 + 1] = rsqrtf(var + 1e-6f);
    }
}

// ---------------------------------------------------------------------------
// 5) GN apply + SiLU, float4
// ---------------------------------------------------------------------------
__global__ void gn_apply_silu_kernel(const float* __restrict__ x, const float* __restrict__ stats,
                                     const float* __restrict__ gamma, const float* __restrict__ beta,
                                     float* __restrict__ out) {
    int idx = blockIdx.x * 256 + threadIdx.x;
    int cg = idx >> 10;
    int c = cg & 255;
    int bg = (cg >> 8) * 32 + (c >> 3);
    float mu = stats[bg * 2], rs = stats[bg * 2 + 1];
    float ga = gamma[c], be = beta[c];
    float4 v = ((const float4*)x)[idx];
    float4 r;
    float t;
    t = fmaf((v.x - mu) * rs, ga, be); r.x = t * (1.f / (1.f + __expf(-t)));
    t = fmaf((v.y - mu) * rs, ga, be); r.y = t * (1.f / (1.f + __expf(-t)));
    t = fmaf((v.z - mu) * rs, ga, be); r.z = t * (1.f / (1.f + __expf(-t)));
    t = fmaf((v.w - mu) * rs, ga, be); r.w = t * (1.f / (1.f + __expf(-t)));
    ((float4*)out)[idx] = r;
}

// ---------------------------------------------------------------------------
// 6) 7x7 depthwise conv, pad 3
// ---------------------------------------------------------------------------
__global__ __launch_bounds__(256)
void dwconv7x7_kernel(const float* __restrict__ x, const float* __restrict__ w,
                      const float* __restrict__ bias, float* __restrict__ out) {
    int bc = blockIdx.x;
    int c = bc & 255;
    const float* p = x + (size_t)bc * NPIX;
    __shared__ float s[70 * 70];
    __shared__ float sw[49];
    for (int t = threadIdx.x; t < 70 * 70; t += 256) {
        int yy = t / 70 - 3, xx = t % 70 - 3;
        s[t] = (yy >= 0 && yy < HW && xx >= 0 && xx < HW) ? p[yy * HW + xx] : 0.f;
    }
    if (threadIdx.x < 49) sw[threadIdx.x] = w[c * 49 + threadIdx.x];
    float bb = bias[c];
    __syncthreads();
    for (int t = threadIdx.x; t < NPIX; t += 256) {
        int y = t >> 6, xq = t & 63;
        float a = bb;
#pragma unroll
        for (int i = 0; i < 7; i++)
#pragma unroll
            for (int j = 0; j < 7; j++)
                a = fmaf(sw[i * 7 + j], s[(y + i) * 70 + xq + j], a);
        out[(size_t)bc * NPIX + t] = a;
    }
}

// ---------------------------------------------------------------------------
// 7) weight split: fp32 -> bf16 hi + bf16 lo
// ---------------------------------------------------------------------------
__global__ void wcvt_kernel(const float* __restrict__ w,
                            __nv_bfloat16* __restrict__ hi, __nv_bfloat16* __restrict__ lo) {
    int i = blockIdx.x * 256 + threadIdx.x;   // over 256*2304
    float f = w[i];
    __nv_bfloat16 h = __float2bfloat16(f);
    hi[i] = h;
    lo[i] = __float2bfloat16(f - __bfloat162float(h));
}

// ---------------------------------------------------------------------------
// 8) DCN im2col -> bf16 hi/lo planes, col[k = (g*32+c)*9+k9][px]
// ---------------------------------------------------------------------------
__global__ __launch_bounds__(256)
void dcn_im2col_kernel(const float* __restrict__ x, const float* __restrict__ co,
                       __nv_bfloat16* __restrict__ chi, __nv_bfloat16* __restrict__ clo) {
    const int b  = blockIdx.z;
    const int gk = blockIdx.y;
    const int g  = gk / 9, k = gk - g * 9;
    const int px = blockIdx.x * 256 + threadIdx.x;
    const int y  = px >> 6, xp = px & 63;

    const float* cob = co + (size_t)b * COUT_CO * NPIX;
    float dy = cob[(size_t)(g * 18 + 2 * k)     * NPIX + px];
    float dx = cob[(size_t)(g * 18 + 2 * k + 1) * NPIX + px];
    float mv = cob[(size_t)(144 + g * 9 + k)    * NPIX + px];
    float m  = 1.f / (1.f + __expf(-mv));

    float py  = (float)(y  - 1 + k / 3) + dy;
    float pxf = (float)(xp - 1 + k % 3) + dx;
    float y0f = floorf(py), x0f = floorf(pxf);
    float wy = py - y0f, wx = pxf - x0f;
    int y0 = (int)y0f, x0 = (int)x0f;

    bool vy0 = (y0 >= 0)     && (y0 < HW);
    bool vy1 = (y0 + 1 >= 0) && (y0 + 1 < HW);
    bool vx0 = (x0 >= 0)     && (x0 < HW);
    bool vx1 = (x0 + 1 >= 0) && (x0 + 1 < HW);

    float m00 = (vy0 && vx0) ? m * (1.f - wy) * (1.f - wx) : 0.f;
    float m01 = (vy0 && vx1) ? m * (1.f - wy) * wx         : 0.f;
    float m10 = (vy1 && vx0) ? m * wy * (1.f - wx)         : 0.f;
    float m11 = (vy1 && vx1) ? m * wy * wx                 : 0.f;

    int iy0 = min(max(y0, 0), HW - 1), iy1 = min(max(y0 + 1, 0), HW - 1);
    int ix0 = min(max(x0, 0), HW - 1), ix1 = min(max(x0 + 1, 0), HW - 1);
    int i00 = iy0 * HW + ix0, i01 = iy0 * HW + ix1;
    int i10 = iy1 * HW + ix0, i11 = iy1 * HW + ix1;

    const float* xb = x + ((size_t)b * C256 + g * 32) * NPIX;
    size_t base = ((size_t)b * DCN_K + (size_t)(g * 32) * 9 + k) * NPIX + px;

#pragma unroll 4
    for (int c = 0; c < 32; c++) {
        const float* xc = xb + (size_t)c * NPIX;
        float v = m00 * xc[i00] + m01 * xc[i01] + m10 * xc[i10] + m11 * xc[i11];
        __nv_bfloat16 h = __float2bfloat16(v);
        size_t idx = base + (size_t)c * 9 * NPIX;
        chi[idx] = h;
        clo[idx] = __float2bfloat16(v - __bfloat162float(h));
    }
}

// ---------------------------------------------------------------------------
// 9) DCN GEMM via mma.sync (bf16 split-precision, SM80-class path — works on
//    plain sm_100 target; tcgen05 is unavailable in this harness build)
//    out[b][oc0..+127][px0..+127] = sum_k W[oc][k] * col[b][k][px]
//    8 warps: warp = 64(oc) x 32(px); K-chunk 32; grid (32, 2, 4)
// ---------------------------------------------------------------------------
__device__ __forceinline__ void ldsm_x4(u32t* r, u32t addr) {
    asm volatile("ldmatrix.sync.aligned.m8n8.x4.shared.b16 {%0,%1,%2,%3}, [%4];"
                 : "=r"(r[0]), "=r"(r[1]), "=r"(r[2]), "=r"(r[3]) : "r"(addr));
}
__device__ __forceinline__ void ldsm_x2t(u32t* r, u32t addr) {
    asm volatile("ldmatrix.sync.aligned.m8n8.x2.trans.shared.b16 {%0,%1}, [%2];"
                 : "=r"(r[0]), "=r"(r[1]) : "r"(addr));
}
__device__ __forceinline__ void mma_bf16(float* d, const u32t* a, const u32t* bq) {
    asm volatile(
        "mma.sync.aligned.m16n8k16.row.col.f32.bf16.bf16.f32 "
        "{%0,%1,%2,%3}, {%4,%5,%6,%7}, {%8,%9}, {%0,%1,%2,%3};"
        : "+f"(d[0]), "+f"(d[1]), "+f"(d[2]), "+f"(d[3])
        : "r"(a[0]), "r"(a[1]), "r"(a[2]), "r"(a[3]), "r"(bq[0]), "r"(bq[1]));
}

__global__ __launch_bounds__(256)
void dcn_mma_kernel(const __nv_bfloat16* __restrict__ whi,
                    const __nv_bfloat16* __restrict__ wlo,
                    const __nv_bfloat16* __restrict__ chi,
                    const __nv_bfloat16* __restrict__ clo,
                    const float* __restrict__ bias,
                    float* __restrict__ out) {
    __shared__ __align__(16) __nv_bfloat16 sA[2][128][40];   // [plane][oc][k]
    __shared__ __align__(16) __nv_bfloat16 sB[2][32][136];   // [plane][k][px]

    const int tid = threadIdx.x, lane = tid & 31, wid = tid >> 5;
    const int px0 = blockIdx.x * 128;
    const int oc0 = blockIdx.y * 128;
    const int b   = blockIdx.z;
    const int wm  = wid & 1;       // 0/1 -> oc half (64)
    const int wn  = wid >> 1;      // 0..3 -> px quarter (32)

    float acc[4][4][4];
#pragma unroll
    for (int mt = 0; mt < 4; mt++)
#pragma unroll
        for (int nt = 0; nt < 4; nt++)
#pragma unroll
            for (int r = 0; r < 4; r++) acc[mt][nt][r] = 0.f;

    // load roles: 2 planes x 128 lanes
    const int lp = tid >> 7;          // 0=hi, 1=lo
    const int lr = tid & 127;
    const __nv_bfloat16* wsrc = (lp ? wlo : whi) + (size_t)(oc0 + lr) * DCN_K;
    const int bkr = lr >> 2, bqb = lr & 3;       // k-row 0..31, px quarter 0..3
    const __nv_bfloat16* csrc = (lp ? clo : chi)
        + (size_t)b * DCN_K * NPIX + px0 + bqb * 32;

    for (int kc = 0; kc < DCN_K; kc += 32) {
        __syncthreads();
        // A: 128 oc rows x 32 k (64B/row), straight copy
        {
            const uint4* s4 = (const uint4*)(wsrc + kc);
            uint4* d4 = (uint4*)&sA[lp][lr][0];
            d4[0] = s4[0]; d4[1] = s4[1]; d4[2] = s4[2]; d4[3] = s4[3];
        }
        // B: 32 k rows x 128 px (256B/row), straight copy (natural layout)
        {
            const uint4* s4 = (const uint4*)(csrc + (size_t)(kc + bkr) * NPIX);
            uint4* d4 = (uint4*)&sB[lp][bkr][bqb * 32];
            d4[0] = s4[0]; d4[1] = s4[1]; d4[2] = s4[2]; d4[3] = s4[3];
        }
        __syncthreads();

#pragma unroll
        for (int kt = 0; kt < 2; kt++) {
            const int kq = kt * 16;
            u32t af[2][4][4], bf[2][4][2];
#pragma unroll
            for (int p = 0; p < 2; p++) {
#pragma unroll
                for (int mt = 0; mt < 4; mt++) {
                    u32t addr = smem_u32(&sA[p][wm * 64 + mt * 16 + (lane & 15)]
                                            [kq + (lane >> 4) * 8]);
                    ldsm_x4(af[p][mt], addr);
                }
#pragma unroll
                for (int nt = 0; nt < 4; nt++) {
                    u32t addr = smem_u32(&sB[p][kq + (lane & 15)][wn * 32 + nt * 8]);
                    ldsm_x2t(bf[p][nt], addr);
                }
            }
#pragma unroll
            for (int mt = 0; mt < 4; mt++)
#pragma unroll
                for (int nt = 0; nt < 4; nt++) {
                    mma_bf16(acc[mt][nt], af[0][mt], bf[0][nt]);   // hi*hi
                    mma_bf16(acc[mt][nt], af[0][mt], bf[1][nt]);   // hi*lo
                    mma_bf16(acc[mt][nt], af[1][mt], bf[0][nt]);   // lo*hi
                }
        }
    }

    // epilogue: direct gmem stores (float2 per half-tile row)
    const int gid = lane >> 2, tig = lane & 3;
#pragma unroll
    for (int mt = 0; mt < 4; mt++) {
        int row = oc0 + wm * 64 + mt * 16 + gid;
        float b0 = bias[row], b1 = bias[row + 8];
        float* o0 = out + ((size_t)b * C256 + row) * NPIX;
        float* o1 = o0 + (size_t)8 * NPIX;
#pragma unroll
        for (int nt = 0; nt < 4; nt++) {
            int col = px0 + wn * 32 + nt * 8 + tig * 2;
            float2 v0 = { acc[mt][nt][0] + b0, acc[mt][nt][1] + b0 };
            float2 v1 = { acc[mt][nt][2] + b1, acc[mt][nt][3] + b1 };
            *(float2*)(o0 + col) = v0;
            *(float2*)(o1 + col) = v1;
        }
    }
}

// ---------------------------------------------------------------------------
// Launch
// ---------------------------------------------------------------------------
extern "C" void kernel_launch(void* const* d_in, const int* in_sizes, int n_in,
                              void* d_out, int out_size) {
    const float* x_main = (const float*)d_in[0];
    const float* prior  = (const float*)d_in[1];
    const float* ds_w = (const float*)d_in[2];  const float* ds_b = (const float*)d_in[3];
    const float* w1a  = (const float*)d_in[4];  const float* b1a  = (const float*)d_in[5];
    const float* g1a  = (const float*)d_in[6];  const float* be1a = (const float*)d_in[7];
    const float* w1b  = (const float*)d_in[8];  const float* b1b  = (const float*)d_in[9];
    const float* g1b  = (const float*)d_in[10]; const float* be1b = (const float*)d_in[11];
    const float* w1c  = (const float*)d_in[12]; const float* b1c  = (const float*)d_in[13];
    const float* w2   = (const float*)d_in[14]; const float* b2   = (const float*)d_in[15];
    const float* g2   = (const float*)d_in[16]; const float* be2  = (const float*)d_in[17];
    const float* co_w = (const float*)d_in[18]; const float* co_b = (const float*)d_in[19];
    const float* dcn_w= (const float*)d_in[20]; const float* dcn_b= (const float*)d_in[21];

    float *bufA, *bufB, *coBuf, *stats;
    __nv_bfloat16 *whi, *wlo, *colhi, *collo;
    cudaGetSymbolAddress((void**)&bufA,  g_bufA);
    cudaGetSymbolAddress((void**)&bufB,  g_bufB);
    cudaGetSymbolAddress((void**)&coBuf, g_co);
    cudaGetSymbolAddress((void**)&stats, g_stats);
    cudaGetSymbolAddress((void**)&whi,   g_whi);
    cudaGetSymbolAddress((void**)&wlo,   g_wlo);
    cudaGetSymbolAddress((void**)&colhi, g_colhi);
    cudaGetSymbolAddress((void**)&collo, g_collo);

    float* out_warp = (float*)d_out;
    float* out_feat = out_warp + (size_t)B4 * IMG;

    const int EL_BLOCKS = (B4 * IMG) / 256;
    const int EL4_BLOCKS = (B4 * IMG) / 1024;

    // weight split for the DCN MMA (independent of the main chain)
    wcvt_kernel<<<(C256 * DCN_K) / 256, 256>>>(dcn_w, whi, wlo);

    // 1. downsample prior -> bufB
    resize_half_kernel<<<EL_BLOCKS, 256>>>(prior, bufB);
    // 2. ds conv 3x3 -> bufA
    conv3x3_kernel<<<dim3(16, 8, B4), 256>>>(bufB, ds_w, ds_b, bufA, C256, C256);
    // 3. 1x1 conv over concat(pr, x_main) -> bufB
    gemm_conv_kernel<<<dim3(8, 8, B4), 256>>>(bufA, x_main, 256, 512, w1a, b1a, bufB, C256);
    // 4. GN + SiLU (in place)
    gn_stats_kernel<<<B4 * 32, 512>>>(bufB, stats);
    gn_apply_silu_kernel<<<EL4_BLOCKS, 256>>>(bufB, stats, g1a, be1a, bufB);
    // 5. 7x7 depthwise -> bufA
    dwconv7x7_kernel<<<B4 * C256, 256>>>(bufB, w1b, b1b, bufA);
    // 6. GN + SiLU (in place)
    gn_stats_kernel<<<B4 * 32, 512>>>(bufA, stats);
    gn_apply_silu_kernel<<<EL4_BLOCKS, 256>>>(bufA, stats, g1b, be1b, bufA);
    // 7. 1x1 conv -> bufB
    gemm_conv_kernel<<<dim3(8, 8, B4), 256>>>(bufA, nullptr, 256, 256, w1c, b1c, bufB, C256);
    // 8. 3x3 conv (w2) -> bufA
    conv3x3_kernel<<<dim3(16, 8, B4), 256>>>(bufB, w2, b2, bufA, C256, C256);
    // 9. GN + SiLU -> offset_feat
    gn_stats_kernel<<<B4 * 32, 512>>>(bufA, stats);
    gn_apply_silu_kernel<<<EL4_BLOCKS, 256>>>(bufA, stats, g2, be2, out_feat);
    // 10. co conv 3x3 (256 -> 216) -> coBuf
    conv3x3_kernel<<<dim3(16, 7, B4), 256>>>(out_feat, co_w, co_b, coBuf, C256, COUT_CO);
    // 11. DCN im2col -> bf16 hi/lo col planes
    dcn_im2col_kernel<<<dim3(16, 72, B4), 256>>>(x_main, coBuf, colhi, collo);
    // 12. DCN GEMM on tensor cores (mma.sync) -> warp
    dcn_mma_kernel<<<dim3(32, 2, B4), 256>>>(whi, wlo, colhi, collo, dcn_b, out_warp);
}

// round 8
// speedup vs baseline: 3.6952x; 2.5456x over previous
#include <cuda_runtime.h>
#include <cuda_bf16.h>
#include <math.h>

#define B4      4
#define C256    256
#define HW      64
#define NPIX    (HW*HW)          // 4096
#define IMG     (C256*NPIX)      // per-batch fp32 elements
#define COUT_CO 216
#define DCN_K   2304             // 256*9

typedef unsigned int u32t;

// ---------------------------------------------------------------------------
// Scratch (no allocation allowed -> __device__ globals)
// ---------------------------------------------------------------------------
__device__ float g_bufA[B4*IMG];
__device__ float g_bufB[B4*IMG];
__device__ float g_co  [B4*COUT_CO*NPIX];
__device__ float g_stats[B4*32*2];
__device__ __nv_bfloat16 g_whi[C256*DCN_K];                 // weight planes (reused per GEMM)
__device__ __nv_bfloat16 g_wlo[C256*DCN_K];
__device__ __nv_bfloat16 g_colhi[(size_t)B4*DCN_K*NPIX];    // B planes (reused per GEMM)
__device__ __nv_bfloat16 g_collo[(size_t)B4*DCN_K*NPIX];

__device__ __forceinline__ u32t smem_u32(const void* p) {
    u32t a;
    asm("{ .reg .u64 t; cvta.to.shared.u64 t, %1; cvt.u32.u64 %0, t; }"
        : "=r"(a) : "l"(p));
    return a;
}

// ---------------------------------------------------------------------------
// 1) bilinear half-downsample = 2x2 average at these shapes
// ---------------------------------------------------------------------------
__global__ void resize_half_kernel(const float* __restrict__ in, float* __restrict__ out) {
    int idx = blockIdx.x * 256 + threadIdx.x;
    int x = idx & 63, y = (idx >> 6) & 63, cg = idx >> 12;
    const float2* p = (const float2*)(in + (size_t)cg * (128 * 128));
    int yy = 2 * y;
    float2 a = p[yy * 64 + x];
    float2 b = p[(yy + 1) * 64 + x];
    out[idx] = 0.25f * (a.x + a.y + b.x + b.y);
}

// ---------------------------------------------------------------------------
// 2) weight split: fp32 -> bf16 hi + lo (n elements)
// ---------------------------------------------------------------------------
__global__ void wcvt_kernel(const float* __restrict__ w, int n,
                            __nv_bfloat16* __restrict__ hi, __nv_bfloat16* __restrict__ lo) {
    int i = blockIdx.x * 256 + threadIdx.x;
    if (i >= n) return;
    float f = w[i];
    __nv_bfloat16 h = __float2bfloat16(f);
    hi[i] = h;
    lo[i] = __float2bfloat16(f - __bfloat162float(h));
}

// ---------------------------------------------------------------------------
// 3) 1x1-conv operand planes: fp32 [K][NPIX] (concat A|B) -> bf16 hi/lo
//    grid (4, K, B4); 256 thr; 4 px per thread
// ---------------------------------------------------------------------------
__global__ void cvt_planes_kernel(const float* __restrict__ A, const float* __restrict__ B,
                                  int splitK,
                                  __nv_bfloat16* __restrict__ hi, __nv_bfloat16* __restrict__ lo) {
    const int b = blockIdx.z, k = blockIdx.y, K = gridDim.y;
    const float* src = (k < splitK)
        ? A + ((size_t)b * splitK + k) * NPIX
        : B + ((size_t)b * (K - splitK) + (k - splitK)) * NPIX;
    int px = (blockIdx.x * 256 + threadIdx.x) * 4;
    float4 v = *(const float4*)(src + px);
    size_t idx = ((size_t)b * K + k) * NPIX + px;
    __nv_bfloat162 h01, h23, l01, l23;
    h01.x = __float2bfloat16(v.x); h01.y = __float2bfloat16(v.y);
    h23.x = __float2bfloat16(v.z); h23.y = __float2bfloat16(v.w);
    l01.x = __float2bfloat16(v.x - __bfloat162float(h01.x));
    l01.y = __float2bfloat16(v.y - __bfloat162float(h01.y));
    l23.x = __float2bfloat16(v.z - __bfloat162float(h23.x));
    l23.y = __float2bfloat16(v.w - __bfloat162float(h23.y));
    *(__nv_bfloat162*)(hi + idx)     = h01;
    *(__nv_bfloat162*)(hi + idx + 2) = h23;
    *(__nv_bfloat162*)(lo + idx)     = l01;
    *(__nv_bfloat162*)(lo + idx + 2) = l23;
}

// ---------------------------------------------------------------------------
// 4) 3x3-conv im2col (pad 1): col[(c*9+tap)][px] = shifted copy -> bf16 hi/lo
//    grid (4, 2304, B4); 256 thr; 4 px per thread
// ---------------------------------------------------------------------------
__global__ void conv_im2col_kernel(const float* __restrict__ x,
                                   __nv_bfloat16* __restrict__ hi,
                                   __nv_bfloat16* __restrict__ lo) {
    const int b = blockIdx.z, k = blockIdx.y;
    const int c = k / 9, tap = k - c * 9;
    const int di = tap / 3 - 1, dj = tap % 3 - 1;
    int px = (blockIdx.x * 256 + threadIdx.x) * 4;
    int y = (px >> 6) + di;
    int xb = (px & 63);
    const float* xc = x + ((size_t)b * C256 + c) * NPIX + y * 64;
    float v[4];
#pragma unroll
    for (int i = 0; i < 4; i++) {
        int xx = xb + i + dj;
        v[i] = (y >= 0 && y < HW && xx >= 0 && xx < HW) ? xc[xx] : 0.f;
    }
    size_t idx = ((size_t)b * DCN_K + k) * NPIX + px;
    __nv_bfloat162 h01, h23, l01, l23;
    h01.x = __float2bfloat16(v[0]); h01.y = __float2bfloat16(v[1]);
    h23.x = __float2bfloat16(v[2]); h23.y = __float2bfloat16(v[3]);
    l01.x = __float2bfloat16(v[0] - __bfloat162float(h01.x));
    l01.y = __float2bfloat16(v[1] - __bfloat162float(h01.y));
    l23.x = __float2bfloat16(v[2] - __bfloat162float(h23.x));
    l23.y = __float2bfloat16(v[3] - __bfloat162float(h23.y));
    *(__nv_bfloat162*)(hi + idx)     = h01;
    *(__nv_bfloat162*)(hi + idx + 2) = h23;
    *(__nv_bfloat162*)(lo + idx)     = l01;
    *(__nv_bfloat162*)(lo + idx + 2) = l23;
}

// ---------------------------------------------------------------------------
// 5) GroupNorm stats
// ---------------------------------------------------------------------------
__global__ __launch_bounds__(512)
void gn_stats_kernel(const float* __restrict__ x, float* __restrict__ stats) {
    int bg = blockIdx.x;
    const float4* p = (const float4*)(x + (size_t)bg * 32768);
    float s = 0.f, ss = 0.f;
    for (int i = threadIdx.x; i < 8192; i += 512) {
        float4 v = p[i];
        s += v.x + v.y + v.z + v.w;
        ss = fmaf(v.x, v.x, fmaf(v.y, v.y, fmaf(v.z, v.z, fmaf(v.w, v.w, ss))));
    }
#pragma unroll
    for (int o = 16; o > 0; o >>= 1) {
        s  += __shfl_down_sync(0xffffffffu, s, o);
        ss += __shfl_down_sync(0xffffffffu, ss, o);
    }
    __shared__ float sh[32];
    int wrp = threadIdx.x >> 5, lane = threadIdx.x & 31;
    if (lane == 0) { sh[wrp] = s; sh[wrp + 16] = ss; }
    __syncthreads();
    if (threadIdx.x == 0) {
        float S = 0.f, SS = 0.f;
#pragma unroll
        for (int i = 0; i < 16; i++) { S += sh[i]; SS += sh[i + 16]; }
        float mu  = S * (1.f / 32768.f);
        float var = SS * (1.f / 32768.f) - mu * mu;
        stats[bg * 2]     = mu;
        stats[bg * 2 + 1] = rsqrtf(var + 1e-6f);
    }
}

// ---------------------------------------------------------------------------
// 6) GN apply + SiLU, float4
// ---------------------------------------------------------------------------
__global__ void gn_apply_silu_kernel(const float* __restrict__ x, const float* __restrict__ stats,
                                     const float* __restrict__ gamma, const float* __restrict__ beta,
                                     float* __restrict__ out) {
    int idx = blockIdx.x * 256 + threadIdx.x;
    int cg = idx >> 10;
    int c = cg & 255;
    int bg = (cg >> 8) * 32 + (c >> 3);
    float mu = stats[bg * 2], rs = stats[bg * 2 + 1];
    float ga = gamma[c], be = beta[c];
    float4 v = ((const float4*)x)[idx];
    float4 r;
    float t;
    t = fmaf((v.x - mu) * rs, ga, be); r.x = t * (1.f / (1.f + __expf(-t)));
    t = fmaf((v.y - mu) * rs, ga, be); r.y = t * (1.f / (1.f + __expf(-t)));
    t = fmaf((v.z - mu) * rs, ga, be); r.z = t * (1.f / (1.f + __expf(-t)));
    t = fmaf((v.w - mu) * rs, ga, be); r.w = t * (1.f / (1.f + __expf(-t)));
    ((float4*)out)[idx] = r;
}

// ---------------------------------------------------------------------------
// 7) 7x7 depthwise conv, pad 3
// ---------------------------------------------------------------------------
__global__ __launch_bounds__(256)
void dwconv7x7_kernel(const float* __restrict__ x, const float* __restrict__ w,
                      const float* __restrict__ bias, float* __restrict__ out) {
    int bc = blockIdx.x;
    int c = bc & 255;
    const float* p = x + (size_t)bc * NPIX;
    __shared__ float s[70 * 70];
    __shared__ float sw[49];
    for (int t = threadIdx.x; t < 70 * 70; t += 256) {
        int yy = t / 70 - 3, xx = t % 70 - 3;
        s[t] = (yy >= 0 && yy < HW && xx >= 0 && xx < HW) ? p[yy * HW + xx] : 0.f;
    }
    if (threadIdx.x < 49) sw[threadIdx.x] = w[c * 49 + threadIdx.x];
    float bb = bias[c];
    __syncthreads();
    for (int t = threadIdx.x; t < NPIX; t += 256) {
        int y = t >> 6, xq = t & 63;
        float a = bb;
#pragma unroll
        for (int i = 0; i < 7; i++)
#pragma unroll
            for (int j = 0; j < 7; j++)
                a = fmaf(sw[i * 7 + j], s[(y + i) * 70 + xq + j], a);
        out[(size_t)bc * NPIX + t] = a;
    }
}

// ---------------------------------------------------------------------------
// 8) DCN im2col -> bf16 hi/lo planes, col[k = (g*32+c)*9+k9][px]
// ---------------------------------------------------------------------------
__global__ __launch_bounds__(256)
void dcn_im2col_kernel(const float* __restrict__ x, const float* __restrict__ co,
                       __nv_bfloat16* __restrict__ chi, __nv_bfloat16* __restrict__ clo) {
    const int b  = blockIdx.z;
    const int gk = blockIdx.y;
    const int g  = gk / 9, k = gk - g * 9;
    const int px = blockIdx.x * 256 + threadIdx.x;
    const int y  = px >> 6, xp = px & 63;

    const float* cob = co + (size_t)b * COUT_CO * NPIX;
    float dy = cob[(size_t)(g * 18 + 2 * k)     * NPIX + px];
    float dx = cob[(size_t)(g * 18 + 2 * k + 1) * NPIX + px];
    float mv = cob[(size_t)(144 + g * 9 + k)    * NPIX + px];
    float m  = 1.f / (1.f + __expf(-mv));

    float py  = (float)(y  - 1 + k / 3) + dy;
    float pxf = (float)(xp - 1 + k % 3) + dx;
    float y0f = floorf(py), x0f = floorf(pxf);
    float wy = py - y0f, wx = pxf - x0f;
    int y0 = (int)y0f, x0 = (int)x0f;

    bool vy0 = (y0 >= 0)     && (y0 < HW);
    bool vy1 = (y0 + 1 >= 0) && (y0 + 1 < HW);
    bool vx0 = (x0 >= 0)     && (x0 < HW);
    bool vx1 = (x0 + 1 >= 0) && (x0 + 1 < HW);

    float m00 = (vy0 && vx0) ? m * (1.f - wy) * (1.f - wx) : 0.f;
    float m01 = (vy0 && vx1) ? m * (1.f - wy) * wx         : 0.f;
    float m10 = (vy1 && vx0) ? m * wy * (1.f - wx)         : 0.f;
    float m11 = (vy1 && vx1) ? m * wy * wx                 : 0.f;

    int iy0 = min(max(y0, 0), HW - 1), iy1 = min(max(y0 + 1, 0), HW - 1);
    int ix0 = min(max(x0, 0), HW - 1), ix1 = min(max(x0 + 1, 0), HW - 1);
    int i00 = iy0 * HW + ix0, i01 = iy0 * HW + ix1;
    int i10 = iy1 * HW + ix0, i11 = iy1 * HW + ix1;

    const float* xb = x + ((size_t)b * C256 + g * 32) * NPIX;
    size_t base = ((size_t)b * DCN_K + (size_t)(g * 32) * 9 + k) * NPIX + px;

#pragma unroll 4
    for (int c = 0; c < 32; c++) {
        const float* xc = xb + (size_t)c * NPIX;
        float v = m00 * xc[i00] + m01 * xc[i01] + m10 * xc[i10] + m11 * xc[i11];
        __nv_bfloat16 h = __float2bfloat16(v);
        size_t idx = base + (size_t)c * 9 * NPIX;
        chi[idx] = h;
        clo[idx] = __float2bfloat16(v - __bfloat162float(h));
    }
}

// ---------------------------------------------------------------------------
// 9) Generalized GEMM via mma.sync (bf16 split-precision)
//    out[b][oc][px] = bias[oc] + sum_k W[oc][k] * Bp[b][k][px]
//    8 warps: warp = 64(oc) x 32(px); K-chunk 32; grid (32, ceil(Cout/128), B4)
// ---------------------------------------------------------------------------
__device__ __forceinline__ void ldsm_x4(u32t* r, u32t addr) {
    asm volatile("ldmatrix.sync.aligned.m8n8.x4.shared.b16 {%0,%1,%2,%3}, [%4];"
                 : "=r"(r[0]), "=r"(r[1]), "=r"(r[2]), "=r"(r[3]) : "r"(addr));
}
__device__ __forceinline__ void ldsm_x2t(u32t* r, u32t addr) {
    asm volatile("ldmatrix.sync.aligned.m8n8.x2.trans.shared.b16 {%0,%1}, [%2];"
                 : "=r"(r[0]), "=r"(r[1]) : "r"(addr));
}
__device__ __forceinline__ void mma_bf16(float* d, const u32t* a, const u32t* bq) {
    asm volatile(
        "mma.sync.aligned.m16n8k16.row.col.f32.bf16.bf16.f32 "
        "{%0,%1,%2,%3}, {%4,%5,%6,%7}, {%8,%9}, {%0,%1,%2,%3};"
        : "+f"(d[0]), "+f"(d[1]), "+f"(d[2]), "+f"(d[3])
        : "r"(a[0]), "r"(a[1]), "r"(a[2]), "r"(a[3]), "r"(bq[0]), "r"(bq[1]));
}

__global__ __launch_bounds__(256)
void mma_gemm_kernel(const __nv_bfloat16* __restrict__ whi,
                     const __nv_bfloat16* __restrict__ wlo,
                     const __nv_bfloat16* __restrict__ bhi,
                     const __nv_bfloat16* __restrict__ blo,
                     const float* __restrict__ bias,
                     float* __restrict__ out, int K, int Cout) {
    __shared__ __align__(16) __nv_bfloat16 sA[2][128][40];   // [plane][oc][k]
    __shared__ __align__(16) __nv_bfloat16 sB[2][32][136];   // [plane][k][px]

    const int tid = threadIdx.x, lane = tid & 31, wid = tid >> 5;
    const int px0 = blockIdx.x * 128;
    const int oc0 = blockIdx.y * 128;
    const int b   = blockIdx.z;
    const int wm  = wid & 1;       // 0/1 -> oc half (64)
    const int wn  = wid >> 1;      // 0..3 -> px quarter (32)

    float acc[4][4][4];
#pragma unroll
    for (int mt = 0; mt < 4; mt++)
#pragma unroll
        for (int nt = 0; nt < 4; nt++)
#pragma unroll
            for (int r = 0; r < 4; r++) acc[mt][nt][r] = 0.f;

    // load roles: 2 planes x 128 lanes
    const int lp = tid >> 7;          // 0=hi, 1=lo
    const int lr = tid & 127;
    const int arow = min(oc0 + lr, Cout - 1);           // clamp for Cout<gridY*128
    const __nv_bfloat16* wsrc = (lp ? wlo : whi) + (size_t)arow * K;
    const int bkr = lr >> 2, bqb = lr & 3;              // k-row 0..31, px quarter 0..3
    const __nv_bfloat16* csrc = (lp ? blo : bhi)
        + (size_t)b * K * NPIX + px0 + bqb * 32;

    for (int kc = 0; kc < K; kc += 32) {
        __syncthreads();
        // A: 128 oc rows x 32 k (64B/row), straight copy
        {
            const uint4* s4 = (const uint4*)(wsrc + kc);
            uint4* d4 = (uint4*)&sA[lp][lr][0];
            d4[0] = s4[0]; d4[1] = s4[1]; d4[2] = s4[2]; d4[3] = s4[3];
        }
        // B: 32 k rows x 128 px (256B/row), straight copy (natural layout)
        {
            const uint4* s4 = (const uint4*)(csrc + (size_t)(kc + bkr) * NPIX);
            uint4* d4 = (uint4*)&sB[lp][bkr][bqb * 32];
            d4[0] = s4[0]; d4[1] = s4[1]; d4[2] = s4[2]; d4[3] = s4[3];
        }
        __syncthreads();

#pragma unroll
        for (int kt = 0; kt < 2; kt++) {
            const int kq = kt * 16;
            u32t af[2][4][4], bf[2][4][2];
#pragma unroll
            for (int p = 0; p < 2; p++) {
#pragma unroll
                for (int mt = 0; mt < 4; mt++) {
                    u32t addr = smem_u32(&sA[p][wm * 64 + mt * 16 + (lane & 15)]
                                            [kq + (lane >> 4) * 8]);
                    ldsm_x4(af[p][mt], addr);
                }
#pragma unroll
                for (int nt = 0; nt < 4; nt++) {
                    u32t addr = smem_u32(&sB[p][kq + (lane & 15)][wn * 32 + nt * 8]);
                    ldsm_x2t(bf[p][nt], addr);
                }
            }
#pragma unroll
            for (int mt = 0; mt < 4; mt++)
#pragma unroll
                for (int nt = 0; nt < 4; nt++) {
                    mma_bf16(acc[mt][nt], af[0][mt], bf[0][nt]);   // hi*hi
                    mma_bf16(acc[mt][nt], af[0][mt], bf[1][nt]);   // hi*lo
                    mma_bf16(acc[mt][nt], af[1][mt], bf[0][nt]);   // lo*hi
                }
        }
    }

    // epilogue: direct gmem stores (float2 per half-tile row), guarded by Cout
    const int gid = lane >> 2, tig = lane & 3;
#pragma unroll
    for (int mt = 0; mt < 4; mt++) {
        int row = oc0 + wm * 64 + mt * 16 + gid;
        float b0 = (row     < Cout) ? bias[row]     : 0.f;
        float b1 = (row + 8 < Cout) ? bias[row + 8] : 0.f;
        float* o0 = out + ((size_t)b * Cout + row) * NPIX;
        float* o1 = o0 + (size_t)8 * NPIX;
#pragma unroll
        for (int nt = 0; nt < 4; nt++) {
            int col = px0 + wn * 32 + nt * 8 + tig * 2;
            float2 v0 = { acc[mt][nt][0] + b0, acc[mt][nt][1] + b0 };
            float2 v1 = { acc[mt][nt][2] + b1, acc[mt][nt][3] + b1 };
            if (row     < Cout) *(float2*)(o0 + col) = v0;
            if (row + 8 < Cout) *(float2*)(o1 + col) = v1;
        }
    }
}

// ---------------------------------------------------------------------------
// Launch
// ---------------------------------------------------------------------------
extern "C" void kernel_launch(void* const* d_in, const int* in_sizes, int n_in,
                              void* d_out, int out_size) {
    const float* x_main = (const float*)d_in[0];
    const float* prior  = (const float*)d_in[1];
    const float* ds_w = (const float*)d_in[2];  const float* ds_b = (const float*)d_in[3];
    const float* w1a  = (const float*)d_in[4];  const float* b1a  = (const float*)d_in[5];
    const float* g1a  = (const float*)d_in[6];  const float* be1a = (const float*)d_in[7];
    const float* w1b  = (const float*)d_in[8];  const float* b1b  = (const float*)d_in[9];
    const float* g1b  = (const float*)d_in[10]; const float* be1b = (const float*)d_in[11];
    const float* w1c  = (const float*)d_in[12]; const float* b1c  = (const float*)d_in[13];
    const float* w2   = (const float*)d_in[14]; const float* b2   = (const float*)d_in[15];
    const float* g2   = (const float*)d_in[16]; const float* be2  = (const float*)d_in[17];
    const float* co_w = (const float*)d_in[18]; const float* co_b = (const float*)d_in[19];
    const float* dcn_w= (const float*)d_in[20]; const float* dcn_b= (const float*)d_in[21];

    float *bufA, *bufB, *coBuf, *stats;
    __nv_bfloat16 *whi, *wlo, *colhi, *collo;
    cudaGetSymbolAddress((void**)&bufA,  g_bufA);
    cudaGetSymbolAddress((void**)&bufB,  g_bufB);
    cudaGetSymbolAddress((void**)&coBuf, g_co);
    cudaGetSymbolAddress((void**)&stats, g_stats);
    cudaGetSymbolAddress((void**)&whi,   g_whi);
    cudaGetSymbolAddress((void**)&wlo,   g_wlo);
    cudaGetSymbolAddress((void**)&colhi, g_colhi);
    cudaGetSymbolAddress((void**)&collo, g_collo);

    float* out_warp = (float*)d_out;
    float* out_feat = out_warp + (size_t)B4 * IMG;

    const int EL_BLOCKS = (B4 * IMG) / 256;
    const int EL4_BLOCKS = (B4 * IMG) / 1024;
    const dim3 IM2COL_G(4, DCN_K, B4);
    const dim3 GEMM_G(32, 2, B4);

    // 1. downsample prior -> bufB
    resize_half_kernel<<<EL_BLOCKS, 256>>>(prior, bufB);

    // 2. ds conv 3x3 (tensor): bufB -> bufA
    wcvt_kernel<<<(C256 * DCN_K + 255) / 256, 256>>>(ds_w, C256 * DCN_K, whi, wlo);
    conv_im2col_kernel<<<IM2COL_G, 256>>>(bufB, colhi, collo);
    mma_gemm_kernel<<<GEMM_G, 256>>>(whi, wlo, colhi, collo, ds_b, bufA, DCN_K, C256);

    // 3. w1a 1x1 over concat(bufA, x_main) (tensor): -> bufB
    wcvt_kernel<<<(C256 * 512 + 255) / 256, 256>>>(w1a, C256 * 512, whi, wlo);
    cvt_planes_kernel<<<dim3(4, 512, B4), 256>>>(bufA, x_main, 256, colhi, collo);
    mma_gemm_kernel<<<GEMM_G, 256>>>(whi, wlo, colhi, collo, b1a, bufB, 512, C256);

    // 4. GN + SiLU (in place)
    gn_stats_kernel<<<B4 * 32, 512>>>(bufB, stats);
    gn_apply_silu_kernel<<<EL4_BLOCKS, 256>>>(bufB, stats, g1a, be1a, bufB);

    // 5. 7x7 depthwise -> bufA
    dwconv7x7_kernel<<<B4 * C256, 256>>>(bufB, w1b, b1b, bufA);

    // 6. GN + SiLU (in place)
    gn_stats_kernel<<<B4 * 32, 512>>>(bufA, stats);
    gn_apply_silu_kernel<<<EL4_BLOCKS, 256>>>(bufA, stats, g1b, be1b, bufA);

    // 7. w1c 1x1 (tensor): bufA -> bufB
    wcvt_kernel<<<(C256 * 256 + 255) / 256, 256>>>(w1c, C256 * 256, whi, wlo);
    cvt_planes_kernel<<<dim3(4, 256, B4), 256>>>(bufA, nullptr, 256, colhi, collo);
    mma_gemm_kernel<<<GEMM_G, 256>>>(whi, wlo, colhi, collo, b1c, bufB, 256, C256);

    // 8. w2 conv 3x3 (tensor): bufB -> bufA
    wcvt_kernel<<<(C256 * DCN_K + 255) / 256, 256>>>(w2, C256 * DCN_K, whi, wlo);
    conv_im2col_kernel<<<IM2COL_G, 256>>>(bufB, colhi, collo);
    mma_gemm_kernel<<<GEMM_G, 256>>>(whi, wlo, colhi, collo, b2, bufA, DCN_K, C256);

    // 9. GN + SiLU -> offset_feat
    gn_stats_kernel<<<B4 * 32, 512>>>(bufA, stats);
    gn_apply_silu_kernel<<<EL4_BLOCKS, 256>>>(bufA, stats, g2, be2, out_feat);

    // 10. co conv 3x3 (tensor, 256->216): out_feat -> coBuf
    wcvt_kernel<<<(COUT_CO * DCN_K + 255) / 256, 256>>>(co_w, COUT_CO * DCN_K, whi, wlo);
    conv_im2col_kernel<<<IM2COL_G, 256>>>(out_feat, colhi, collo);
    mma_gemm_kernel<<<GEMM_G, 256>>>(whi, wlo, colhi, collo, co_b, coBuf, DCN_K, COUT_CO);

    // 11. DCN im2col -> bf16 hi/lo col planes
    wcvt_kernel<<<(C256 * DCN_K + 255) / 256, 256>>>(dcn_w, C256 * DCN_K, whi, wlo);
    dcn_im2col_kernel<<<dim3(16, 72, B4), 256>>>(x_main, coBuf, colhi, collo);

    // 12. DCN GEMM (tensor) -> warp
    mma_gemm_kernel<<<GEMM_G, 256>>>(whi, wlo, colhi, collo, dcn_b, out_warp, DCN_K, C256);
}